// round 1
// baseline (speedup 1.0000x reference)
#include <cuda_runtime.h>
#include <cuda_bf16.h>

#define H     488
#define AW    484          // H - 5 + 1
#define KCL   6
#define NB    32
#define ITERS 10

// Scratch (allocation-free: __device__ globals)
__device__ float g_hm[NB * H * H];          // mutable working heatmap
__device__ float g_colsum[NB * AW * H];     // vertical 5-sums: [AW rows][H cols]
__device__ float g_clusters[NB * KCL * 2];  // (y, x) float seeds from greedy

// ---------------------------------------------------------------------------
// Phase 1: greedy peak extraction. One block per batch, 1024 threads,
// 6 sequential peaks with block-wide reductions.
// ---------------------------------------------------------------------------
__global__ __launch_bounds__(1024)
void greedy_kernel(const float* __restrict__ in) {
    const int b   = blockIdx.x;
    const int tid = threadIdx.x;
    const float* src = in + (size_t)b * H * H;
    float* hm = g_hm     + (size_t)b * H * H;
    float* cs = g_colsum + (size_t)b * AW * H;

    __shared__ float rv[1024];
    __shared__ int   ri[1024];
    __shared__ float s_maxv;
    __shared__ int   s_r, s_c;

    // copy input into mutable scratch (full overwrite every launch -> deterministic)
    for (int i = tid; i < H * H; i += 1024) hm[i] = src[i];
    __syncthreads();

    // column sums: cs[i][j] = sum_{di=0..4} hm[i+di][j], via register ring (fixed add order)
    for (int j = tid; j < H; j += 1024) {
        float w0 = hm[0 * H + j], w1 = hm[1 * H + j],
              w2 = hm[2 * H + j], w3 = hm[3 * H + j], w4;
        for (int i = 0; i < AW; i++) {
            w4 = hm[(i + 4) * H + j];
            cs[i * H + j] = w0 + w1 + w2 + w3 + w4;
            w0 = w1; w1 = w2; w2 = w3; w3 = w4;
        }
    }
    __syncthreads();

    for (int it = 0; it < KCL; it++) {
        // ---- argmax over 5x5 box sums (unnormalized: /25 is argmax-invariant)
        // 2 threads per row, each 242 outputs, sliding 5-window in registers.
        float bv = -1.0f; int bi = 0x7fffffff;
        {
            int r = tid >> 1;
            if (r < AW) {
                int j0 = (tid & 1) * 242;
                const float* row = cs + r * H;
                float w0 = row[j0], w1 = row[j0 + 1], w2 = row[j0 + 2], w3 = row[j0 + 3], w4;
                #pragma unroll 4
                for (int j = j0; j < j0 + 242; j++) {
                    w4 = row[j + 4];
                    float v = w0 + w1 + w2 + w3 + w4;
                    if (v > bv) { bv = v; bi = r * AW + j; }  // strict > keeps first occurrence
                    w0 = w1; w1 = w2; w2 = w3; w3 = w4;
                }
            }
        }
        rv[tid] = bv; ri[tid] = bi;
        __syncthreads();
        for (int s = 512; s > 0; s >>= 1) {
            if (tid < s) {
                if (rv[tid + s] > rv[tid] ||
                    (rv[tid + s] == rv[tid] && ri[tid + s] < ri[tid])) {
                    rv[tid] = rv[tid + s]; ri[tid] = ri[tid + s];
                }
            }
            __syncthreads();
        }
        if (tid == 0) {
            int flat = ri[0];
            int r = flat / AW, c = flat % AW;
            s_r = r; s_c = c;
            float mv = -1.0f;
            #pragma unroll
            for (int di = 0; di < 5; di++)
                #pragma unroll
                for (int dj = 0; dj < 5; dj++)
                    mv = fmaxf(mv, hm[(r + di) * H + (c + dj)]);
            s_maxv = mv;
        }
        __syncthreads();

        // ---- global first-occurrence scan: argmax(hm == max_val)
        // (required: uniform fp32 duplicates are probable enough to change results)
        {
            float mv = s_maxv;
            int mi = 0x7fffffff;
            for (int i = tid; i < H * H; i += 1024)
                if (hm[i] == mv && i < mi) mi = i;   // ascending -> per-thread min
            ri[tid] = mi;
            __syncthreads();
            for (int s = 512; s > 0; s >>= 1) {
                if (tid < s) { if (ri[tid + s] < ri[tid]) ri[tid] = ri[tid + s]; }
                __syncthreads();
            }
            if (tid == 0) {
                int fh = ri[0];
                g_clusters[(b * KCL + it) * 2 + 0] = (float)(fh / H);
                g_clusters[(b * KCL + it) * 2 + 1] = (float)(fh % H);
            }
        }

        // ---- zero the 5x5 window
        if (tid < 25) hm[(s_r + tid / 5) * H + (s_c + tid % 5)] = 0.0f;
        __syncthreads();

        // ---- incremental colsum repair: cols c..c+4, rows r-4..r+4 (<=45 entries)
        {
            int r0 = max(0, s_r - 4), r1 = min(AW - 1, s_r + 4);
            int total = (r1 - r0 + 1) * 5;
            if (tid < total) {
                int rr = r0 + tid / 5;
                int cc = s_c + tid % 5;
                cs[rr * H + cc] = hm[rr * H + cc] + hm[(rr + 1) * H + cc] +
                                  hm[(rr + 2) * H + cc] + hm[(rr + 3) * H + cc] +
                                  hm[(rr + 4) * H + cc];
            }
        }
        __syncthreads();
    }
}

// ---------------------------------------------------------------------------
// Phase 2+3: mean-shift refinement (THR=12 => only a 26x26 bbox per cluster
// contributes; w = hm * m / d^2, one sqrt per point), then rounding +
// clamped 4x4 confidence windows on the ORIGINAL heatmap.
// Deterministic: fixed-order warp-shuffle + per-warp partials, no atomics.
// ---------------------------------------------------------------------------
__global__ __launch_bounds__(256)
void refine_kernel(const float* __restrict__ in, float* __restrict__ out) {
    const int b   = blockIdx.x;
    const int tid = threadIdx.x;
    const int wid = tid >> 5;
    const float* hm = in + (size_t)b * H * H;

    __shared__ float cly[KCL], clx[KCL];
    __shared__ float pY[KCL][8], pX[KCL][8], pW[KCL][8];

    if (tid < KCL) {
        cly[tid] = g_clusters[(b * KCL + tid) * 2 + 0];
        clx[tid] = g_clusters[(b * KCL + tid) * 2 + 1];
    }
    __syncthreads();

    for (int it = 0; it < ITERS; it++) {
        for (int k = 0; k < KCL; k++) {
            float cy = cly[k], cx = clx[k];
            int y0 = max(0, (int)floorf(cy - 12.0f));
            int y1 = min(H - 1, (int)ceilf(cy + 12.0f));
            int x0 = max(0, (int)floorf(cx - 12.0f));
            int x1 = min(H - 1, (int)ceilf(cx + 12.0f));
            int w  = x1 - x0 + 1;
            int nb = (y1 - y0 + 1) * w;

            float sy = 0.0f, sx = 0.0f, sw = 0.0f;
            for (int t = tid; t < nb; t += 256) {
                int y = y0 + t / w;
                int x = x0 + t % w;
                float dy = (float)y - cy, dx = (float)x - cx;
                float d2 = fmaxf(dy * dy + dx * dx, 1e-6f);
                if (d2 < 144.0f) {
                    float m2 = d2;
                    #pragma unroll
                    for (int k2 = 0; k2 < KCL; k2++) {
                        float ey = (float)y - cly[k2], ex = (float)x - clx[k2];
                        m2 = fminf(m2, fmaxf(ey * ey + ex * ex, 1e-6f));
                    }
                    float wgt = hm[y * H + x] * sqrtf(m2) / d2;
                    sy += wgt * (float)y;
                    sx += wgt * (float)x;
                    sw += wgt;
                }
            }
            #pragma unroll
            for (int off = 16; off; off >>= 1) {
                sy += __shfl_down_sync(0xffffffffu, sy, off);
                sx += __shfl_down_sync(0xffffffffu, sx, off);
                sw += __shfl_down_sync(0xffffffffu, sw, off);
            }
            if ((tid & 31) == 0) { pY[k][wid] = sy; pX[k][wid] = sx; pW[k][wid] = sw; }
        }
        __syncthreads();
        if (tid < KCL) {
            float ay = 0.0f, ax = 0.0f, aw = 0.0f;
            #pragma unroll
            for (int wI = 0; wI < 8; wI++) { ay += pY[tid][wI]; ax += pX[tid][wI]; aw += pW[tid][wI]; }
            cly[tid] = ay / aw;
            clx[tid] = ax / aw;
        }
        __syncthreads();
    }

    if (tid < KCL) {
        int iy = (int)rintf(cly[tid]);   // rintf = round-half-to-even, matches jnp.round
        int ix = (int)rintf(clx[tid]);
        out[(b * KCL + tid) * 2 + 0] = (float)iy;
        out[(b * KCL + tid) * 2 + 1] = (float)ix;
        // dynamic_slice clamp semantics: start in [0, H-4]
        int sy0 = min(max(iy - 2, 0), H - 4);
        int sx0 = min(max(ix - 2, 0), H - 4);
        float c = 0.0f;
        #pragma unroll
        for (int di = 0; di < 4; di++)
            #pragma unroll
            for (int dj = 0; dj < 4; dj++)
                c += hm[(sy0 + di) * H + (sx0 + dj)];
        out[NB * KCL * 2 + b * KCL + tid] = c;
    }
}

extern "C" void kernel_launch(void* const* d_in, const int* in_sizes, int n_in,
                              void* d_out, int out_size) {
    const float* hm = (const float*)d_in[0];
    float* out = (float*)d_out;
    greedy_kernel<<<NB, 1024>>>(hm);
    refine_kernel<<<NB, 256>>>(hm, out);
}

// round 2
// speedup vs baseline: 2.9837x; 2.9837x over previous
#include <cuda_runtime.h>
#include <cuda_bf16.h>

#define H      488
#define AW     484          // H - 5 + 1
#define KCL    6
#define NB     32
#define ITERS  10
#define NCHUNK 8
#define CROWS  61           // ceil(484/8) rows of colsum per chunk; 61*8=488 for copy
#define EQ4    7442         // (488*488/4)/8 float4 elements per eq-scan chunk

// Scratch (allocation-free: __device__ globals)
__device__ float g_hm[NB * H * H];            // mutable working heatmap
__device__ float g_colsum[NB * AW * H];       // vertical 5-sums: [AW rows][H cols]
__device__ float g_clusters[NB * KCL * 2];    // (y, x) float seeds from greedy
// per-batch peak state
__device__ float g_wv[NB * 25];               // saved pre-zero window values
__device__ int   g_wr[NB], g_wc[NB];
__device__ float g_maxv[NB];
// per-(batch,chunk) scan partials
__device__ float g_partAv[NB * NCHUNK];
__device__ int   g_partAi[NB * NCHUNK];
__device__ int   g_partE[NB * NCHUNK];

// ---------------------------------------------------------------------------
// Prep: copy input -> g_hm, build column 5-sums. grid (NB, NCHUNK) x 256.
// colsum reads the ORIGINAL input (same values), so no intra-kernel deps.
// ---------------------------------------------------------------------------
__global__ __launch_bounds__(256)
void prep_kernel(const float* __restrict__ in) {
    const int b  = blockIdx.x, cb = blockIdx.y, tid = threadIdx.x;
    const float* src = in + (size_t)b * H * H;
    float* hm = g_hm     + (size_t)b * H * H;
    float* cs = g_colsum + (size_t)b * AW * H;

    // copy rows [61*cb, min(488, +61)) as float4
    {
        int r0 = CROWS * cb, r1 = min(H, r0 + CROWS);
        const float4* s4 = (const float4*)src;
        float4* d4 = (float4*)hm;
        int e0 = r0 * (H / 4), e1 = r1 * (H / 4);
        for (int i = e0 + tid; i < e1; i += 256) d4[i] = s4[i];
    }
    // colsum rows [61*cb, min(484, +61))
    {
        int i0 = CROWS * cb, i1 = min(AW, i0 + CROWS);
        for (int j = tid; j < H; j += 256) {
            float w0 = src[(i0 + 0) * H + j], w1 = src[(i0 + 1) * H + j],
                  w2 = src[(i0 + 2) * H + j], w3 = src[(i0 + 3) * H + j], w4;
            for (int i = i0; i < i1; i++) {
                w4 = src[(i + 4) * H + j];
                cs[i * H + j] = w0 + w1 + w2 + w3 + w4;
                w0 = w1; w1 = w2; w2 = w3; w3 = w4;
            }
        }
    }
}

// ---------------------------------------------------------------------------
// Scan: fused (a) sliding 5x5 box-sum argmax over colsum (current iteration)
//       (b) first-occurrence scan of hm == prev maxv with zeroed-window
//           override (finishes PREVIOUS iteration's point).
// grid (NB, NCHUNK) x 256.
// ---------------------------------------------------------------------------
__global__ __launch_bounds__(256)
void scan_kernel(int do_eq, int do_arg) {
    const int b  = blockIdx.x, cb = blockIdx.y, tid = threadIdx.x;
    const float* hm = g_hm     + (size_t)b * H * H;
    const float* cs = g_colsum + (size_t)b * AW * H;

    __shared__ float rv[256];
    __shared__ int   ri[256];
    __shared__ float s_wv[25];
    __shared__ float s_mv;
    __shared__ int   s_r, s_c;

    if (do_eq && tid < 25) s_wv[tid] = g_wv[b * 25 + tid];
    if (do_eq && tid == 0) { s_mv = g_maxv[b]; s_r = g_wr[b]; s_c = g_wc[b]; }
    __syncthreads();

    // ---- (b) equality scan, float4, chunk of 29768 elems
    if (do_eq) {
        const float4* hm4 = (const float4*)hm;
        const float mv = s_mv;
        const int wr = s_r, wc = s_c;
        int mi = 0x7fffffff;
        int b0 = cb * EQ4;
        for (int t4 = b0 + tid; t4 < b0 + EQ4; t4 += 256) {
            float4 v = hm4[t4];
            int idx = t4 * 4;
            #pragma unroll
            for (int u = 0; u < 4; u++) {
                float val = (u == 0) ? v.x : (u == 1) ? v.y : (u == 2) ? v.z : v.w;
                int id = idx + u;
                int y = id / H, x = id - y * H;
                unsigned dy = (unsigned)(y - wr), dx = (unsigned)(x - wc);
                if (dy < 5u && dx < 5u) val = s_wv[dy * 5 + dx];
                if (val == mv && id < mi) mi = id;
            }
        }
        ri[tid] = mi;
        __syncthreads();
        for (int s = 128; s > 0; s >>= 1) {
            if (tid < s) { if (ri[tid + s] < ri[tid]) ri[tid] = ri[tid + s]; }
            __syncthreads();
        }
        if (tid == 0) g_partE[b * NCHUNK + cb] = ri[0];
        __syncthreads();
    }

    // ---- (a) box-sum argmax, sliding window, 4 threads per row x 121 windows
    if (do_arg) {
        float bv = -1.0f; int bi = 0x7fffffff;
        int i0 = CROWS * cb, i1 = min(AW, i0 + CROWS);
        int row = i0 + (tid >> 2);
        if (row < i1) {
            int j0 = (tid & 3) * 121;
            const float* r = cs + row * H;
            float w0 = r[j0], w1 = r[j0 + 1], w2 = r[j0 + 2], w3 = r[j0 + 3], w4;
            #pragma unroll 4
            for (int j = j0; j < j0 + 121; j++) {
                w4 = r[j + 4];
                float v = w0 + w1 + w2 + w3 + w4;
                if (v > bv) { bv = v; bi = row * AW + j; }   // strict > -> first occurrence
                w0 = w1; w1 = w2; w2 = w3; w3 = w4;
            }
        }
        rv[tid] = bv; ri[tid] = bi;
        __syncthreads();
        for (int s = 128; s > 0; s >>= 1) {
            if (tid < s) {
                if (rv[tid + s] > rv[tid] ||
                    (rv[tid + s] == rv[tid] && ri[tid + s] < ri[tid])) {
                    rv[tid] = rv[tid + s]; ri[tid] = ri[tid + s];
                }
            }
            __syncthreads();
        }
        if (tid == 0) { g_partAv[b * NCHUNK + cb] = rv[0]; g_partAi[b * NCHUNK + cb] = ri[0]; }
    }
}

// ---------------------------------------------------------------------------
// Finalize: reduce chunk partials. (eq) emit previous iteration's point.
// (arg) pick window, save+zero it, repair colsum, record maxv. grid NB x 64.
// ---------------------------------------------------------------------------
__global__ __launch_bounds__(64)
void final_kernel(int do_eq, int slot_eq, int do_arg) {
    const int b = blockIdx.x, tid = threadIdx.x;
    float* hm = g_hm     + (size_t)b * H * H;
    float* cs = g_colsum + (size_t)b * AW * H;

    __shared__ float swin[25];
    __shared__ int s_r, s_c;

    if (do_eq && tid == 32) {          // warp 1: independent of argmax path
        int fh = 0x7fffffff;
        #pragma unroll
        for (int i = 0; i < NCHUNK; i++) fh = min(fh, g_partE[b * NCHUNK + i]);
        g_clusters[(b * KCL + slot_eq) * 2 + 0] = (float)(fh / H);
        g_clusters[(b * KCL + slot_eq) * 2 + 1] = (float)(fh % H);
    }

    if (do_arg) {
        if (tid == 0) {
            float bv = -1.0f; int bi = 0x7fffffff;
            #pragma unroll
            for (int i = 0; i < NCHUNK; i++) {
                float v = g_partAv[b * NCHUNK + i];
                int   ix = g_partAi[b * NCHUNK + i];
                if (v > bv || (v == bv && ix < bi)) { bv = v; bi = ix; }
            }
            s_r = bi / AW; s_c = bi % AW;
        }
        __syncthreads();
        if (tid < 25) swin[tid] = hm[(s_r + tid / 5) * H + (s_c + tid % 5)];
        __syncthreads();
        if (tid == 0) {
            float mv = -1.0f;
            #pragma unroll
            for (int i = 0; i < 25; i++) mv = fmaxf(mv, swin[i]);
            g_maxv[b] = mv; g_wr[b] = s_r; g_wc[b] = s_c;
        }
        if (tid < 25) {
            g_wv[b * 25 + tid] = swin[tid];
            hm[(s_r + tid / 5) * H + (s_c + tid % 5)] = 0.0f;
        }
        __syncthreads();
        {
            int r0 = max(0, s_r - 4), r1 = min(AW - 1, s_r + 4);
            int total = (r1 - r0 + 1) * 5;
            if (tid < total) {
                int rr = r0 + tid / 5, cc = s_c + tid % 5;
                cs[rr * H + cc] = hm[rr * H + cc] + hm[(rr + 1) * H + cc] +
                                  hm[(rr + 2) * H + cc] + hm[(rr + 3) * H + cc] +
                                  hm[(rr + 4) * H + cc];
            }
        }
    }
}

// ---------------------------------------------------------------------------
// Refine: warp-per-cluster mean shift (THR=12 -> 26x26 bbox, w = hm*m/d^2),
// then rounding + clamped 4x4 confidence windows on the ORIGINAL heatmap.
// grid NB x 192 (6 warps). Deterministic shuffle-tree reductions.
// ---------------------------------------------------------------------------
__global__ __launch_bounds__(192)
void refine_kernel(const float* __restrict__ in, float* __restrict__ out) {
    const int b = blockIdx.x, tid = threadIdx.x;
    const int wid = tid >> 5, lane = tid & 31;
    const float* hm = in + (size_t)b * H * H;

    __shared__ float cly[KCL], clx[KCL], nly[KCL], nlx[KCL];

    if (tid < KCL) {
        cly[tid] = g_clusters[(b * KCL + tid) * 2 + 0];
        clx[tid] = g_clusters[(b * KCL + tid) * 2 + 1];
    }
    __syncthreads();

    for (int it = 0; it < ITERS; it++) {
        {
            const int k = wid;   // one warp per cluster, exactly 6 warps
            float cy = cly[k], cx = clx[k];
            int y0 = max(0, (int)floorf(cy - 12.0f));
            int y1 = min(H - 1, (int)ceilf(cy + 12.0f));
            int x0 = max(0, (int)floorf(cx - 12.0f));
            int x1 = min(H - 1, (int)ceilf(cx + 12.0f));
            int w  = x1 - x0 + 1;
            int nb = (y1 - y0 + 1) * w;

            float sy = 0.0f, sx = 0.0f, sw = 0.0f;
            for (int t = lane; t < nb; t += 32) {
                int y = y0 + t / w;
                int x = x0 + t % w;
                float dy = (float)y - cy, dx = (float)x - cx;
                float d2 = fmaxf(dy * dy + dx * dx, 1e-6f);
                if (d2 < 144.0f) {
                    float m2 = d2;
                    #pragma unroll
                    for (int k2 = 0; k2 < KCL; k2++) {
                        float ey = (float)y - cly[k2], ex = (float)x - clx[k2];
                        m2 = fminf(m2, fmaxf(ey * ey + ex * ex, 1e-6f));
                    }
                    float wgt = hm[y * H + x] * sqrtf(m2) / d2;
                    sy += wgt * (float)y;
                    sx += wgt * (float)x;
                    sw += wgt;
                }
            }
            #pragma unroll
            for (int off = 16; off; off >>= 1) {
                sy += __shfl_down_sync(0xffffffffu, sy, off);
                sx += __shfl_down_sync(0xffffffffu, sx, off);
                sw += __shfl_down_sync(0xffffffffu, sw, off);
            }
            if (lane == 0) { nly[k] = sy / sw; nlx[k] = sx / sw; }
        }
        __syncthreads();
        if (tid < KCL) { cly[tid] = nly[tid]; clx[tid] = nlx[tid]; }
        __syncthreads();
    }

    if (tid < KCL) {
        int iy = (int)rintf(cly[tid]);   // round-half-to-even == jnp.round
        int ix = (int)rintf(clx[tid]);
        out[(b * KCL + tid) * 2 + 0] = (float)iy;
        out[(b * KCL + tid) * 2 + 1] = (float)ix;
        int sy0 = min(max(iy - 2, 0), H - 4);   // dynamic_slice clamp
        int sx0 = min(max(ix - 2, 0), H - 4);
        float c = 0.0f;
        #pragma unroll
        for (int di = 0; di < 4; di++)
            #pragma unroll
            for (int dj = 0; dj < 4; dj++)
                c += hm[(sy0 + di) * H + (sx0 + dj)];
        out[NB * KCL * 2 + b * KCL + tid] = c;
    }
}

extern "C" void kernel_launch(void* const* d_in, const int* in_sizes, int n_in,
                              void* d_out, int out_size) {
    const float* hm = (const float*)d_in[0];
    float* out = (float*)d_out;

    prep_kernel<<<dim3(NB, NCHUNK), 256>>>(hm);
    for (int it = 0; it < KCL; it++) {
        scan_kernel<<<dim3(NB, NCHUNK), 256>>>(it > 0 ? 1 : 0, 1);
        final_kernel<<<NB, 64>>>(it > 0 ? 1 : 0, it - 1, 1);
    }
    scan_kernel<<<dim3(NB, NCHUNK), 256>>>(1, 0);     // finish last point
    final_kernel<<<NB, 64>>>(1, KCL - 1, 0);
    refine_kernel<<<NB, 192>>>(hm, out);
}

// round 3
// speedup vs baseline: 5.0711x; 1.6996x over previous
#include <cuda_runtime.h>
#include <cuda_bf16.h>

#define H      488
#define AW     484          // H - 5 + 1
#define KCL    6
#define NB     32
#define ITERS  10
#define SEG    121          // 484 = 4 * 121 windows per row, 4 segments
#define NSEG   4
#define NPART  (AW * NSEG)  // 1936 partials per batch
#define CR0    16           // rows per scan0 chunk
#define NCH0   31           // ceil(484/16)
#define NE4    (H * H / 4)  // 59536 float4 per batch
#define NCHE   32
#define CE4    1861         // ceil(59536/32)

// Scratch (allocation-free: __device__ globals)
__device__ float g_colsum[NB * AW * H];     // vertical 5-sums
__device__ float g_pv[NB * NPART];          // per-(row,seg) argmax value
__device__ int   g_pi[NB * NPART];          // per-(row,seg) argmax flat window idx
__device__ int   g_wr[NB * KCL], g_wc[NB * KCL];
__device__ float g_maxv[NB * KCL];
__device__ int   g_eqmin[NB * KCL];         // first-occurrence flat hm index

__device__ __forceinline__ void better(float v, int i, float& bv, int& bi) {
    if (v > bv || (v == bv && i < bi)) { bv = v; bi = i; }
}

// ---------------------------------------------------------------------------
// scan0: input -> colsum (global) + initial argmax partials. grid (NB, 31).
// ---------------------------------------------------------------------------
__global__ __launch_bounds__(256)
void scan0_kernel(const float* __restrict__ in) {
    const int b = blockIdx.x, cb = blockIdx.y, tid = threadIdx.x;
    const float* src = in + (size_t)b * H * H;
    float* cs = g_colsum + (size_t)b * AW * H;

    __shared__ float s_cs[CR0][H];

    const int R0 = CR0 * cb, R1 = min(AW, R0 + CR0);

    // column 5-sums for rows [R0, R1): left-assoc register ring
    for (int j = tid; j < H; j += 256) {
        float w0 = src[(R0 + 0) * H + j], w1 = src[(R0 + 1) * H + j],
              w2 = src[(R0 + 2) * H + j], w3 = src[(R0 + 3) * H + j], w4;
        for (int i = R0; i < R1; i++) {
            w4 = src[(i + 4) * H + j];
            float s = w0 + w1 + w2 + w3 + w4;
            s_cs[i - R0][j] = s;
            cs[i * H + j] = s;
            w0 = w1; w1 = w2; w2 = w3; w3 = w4;
        }
    }
    __syncthreads();

    // partials: 64 (row,seg) pairs, 4 sub-threads each
    const int pair = tid >> 2, sub = tid & 3;
    const int lr = pair >> 2, sg = pair & 3;
    const int nrows = R1 - R0;

    float bv = -1.0f; int bi = 0x7fffffff;
    if (lr < nrows) {
        const float* row = s_cs[lr];
        const int jbeg = sg * SEG;
        for (int j = jbeg + sub; j < jbeg + SEG; j += 4) {
            float v = row[j] + row[j + 1] + row[j + 2] + row[j + 3] + row[j + 4];
            better(v, (R0 + lr) * AW + j, bv, bi);
        }
    }
    #pragma unroll
    for (int off = 2; off; off >>= 1) {
        float ov = __shfl_down_sync(0xffffffffu, bv, off);
        int   oi = __shfl_down_sync(0xffffffffu, bi, off);
        better(ov, oi, bv, bi);
    }
    if (sub == 0 && lr < nrows) {
        g_pv[b * NPART + (R0 + lr) * NSEG + sg] = bv;
        g_pi[b * NPART + (R0 + lr) * NSEG + sg] = bi;
    }
}

// ---------------------------------------------------------------------------
// final6: all 6 greedy extractions in one kernel. grid NB x 256.
// Partials live in smem; colsum repaired in global; window coverage replaces
// heatmap mutation (value = orig unless covered by an earlier window -> 0).
// ---------------------------------------------------------------------------
__global__ __launch_bounds__(256)
void final6_kernel(const float* __restrict__ in) {
    const int b = blockIdx.x, tid = threadIdx.x;
    const float* src = in + (size_t)b * H * H;
    float* cs = g_colsum + (size_t)b * AW * H;

    __shared__ float s_pv[NPART];
    __shared__ int   s_pi[NPART];
    __shared__ float s_rv[256];
    __shared__ int   s_ri[256];
    __shared__ float s_win[25];
    __shared__ int   s_wr[KCL], s_wc[KCL];
    __shared__ float s_mv[KCL];
    __shared__ int   s_r, s_c;

    for (int i = tid; i < NPART; i += 256) {
        s_pv[i] = g_pv[b * NPART + i];
        s_pi[i] = g_pi[b * NPART + i];
    }
    if (tid < KCL) g_eqmin[b * KCL + tid] = 0x7fffffff;   // init for eq pass
    __syncthreads();

    for (int it = 0; it < KCL; it++) {
        // ---- A: global argmax over 1936 smem partials
        float bv = -1.0f; int bi = 0x7fffffff;
        for (int i = tid; i < NPART; i += 256) better(s_pv[i], s_pi[i], bv, bi);
        s_rv[tid] = bv; s_ri[tid] = bi;
        __syncthreads();
        for (int s = 128; s > 0; s >>= 1) {
            if (tid < s) {
                if (s_rv[tid + s] > s_rv[tid] ||
                    (s_rv[tid + s] == s_rv[tid] && s_ri[tid + s] < s_ri[tid])) {
                    s_rv[tid] = s_rv[tid + s]; s_ri[tid] = s_ri[tid + s];
                }
            }
            __syncthreads();
        }
        if (tid == 0) { s_r = s_ri[0] / AW; s_c = s_ri[0] % AW; }
        __syncthreads();
        const int r = s_r, c = s_c;

        // ---- B: window max (value = orig unless covered by window j < it)
        if (tid < 25) {
            int y = r + tid / 5, x = c + tid % 5;
            float v = src[y * H + x];
            for (int j = 0; j < it; j++)
                if ((unsigned)(y - s_wr[j]) < 5u && (unsigned)(x - s_wc[j]) < 5u) v = 0.0f;
            s_win[tid] = v;
        }
        __syncthreads();
        if (tid == 0) {
            float mv = -1.0f;
            #pragma unroll
            for (int i = 0; i < 25; i++) mv = fmaxf(mv, s_win[i]);
            s_mv[it] = mv; s_wr[it] = r; s_wc[it] = c;
        }

        // ---- C: colsum repair (coverage includes current window)
        const int r0c = max(0, r - 4), r1c = min(AW - 1, r + 4);
        {
            int nc = (r1c - r0c + 1) * 5;
            if (tid < nc) {
                int rr = r0c + tid / 5, cc = c + tid % 5;
                float s = 0.0f;
                #pragma unroll
                for (int d = 0; d < 5; d++) {
                    int y = rr + d;
                    float v = src[y * H + cc];
                    // covered by any window j <= it ?  (current window = (r,c))
                    if ((unsigned)(y - r) < 5u && (unsigned)(cc - c) < 5u) v = 0.0f;
                    for (int j = 0; j < it; j++)
                        if ((unsigned)(y - s_wr[j]) < 5u && (unsigned)(cc - s_wc[j]) < 5u) v = 0.0f;
                    s = s + v;   // left-assoc, matches scan0 ring
                }
                cs[rr * H + cc] = s;
            }
        }
        __syncthreads();

        // ---- D: recompute affected partials (<= 9 rows x 2 segs)
        {
            const int jlo = max(0, c - 4), jhi = min(AW - 1, c + 4);
            const int s0 = jlo / SEG, s1 = jhi / SEG;
            const int nsegs = s1 - s0 + 1;
            const int npairs = (r1c - r0c + 1) * nsegs;
            const int warp = tid >> 5, lane = tid & 31;
            for (int p = warp; p < npairs; p += 8) {
                int rr = r0c + p / nsegs, sg = s0 + p % nsegs;
                const float* row = cs + rr * H;
                float bv2 = -1.0f; int bi2 = 0x7fffffff;
                for (int j = sg * SEG + lane; j < sg * SEG + SEG; j += 32) {
                    float v = row[j] + row[j + 1] + row[j + 2] + row[j + 3] + row[j + 4];
                    better(v, rr * AW + j, bv2, bi2);
                }
                #pragma unroll
                for (int off = 16; off; off >>= 1) {
                    float ov = __shfl_down_sync(0xffffffffu, bv2, off);
                    int   oi = __shfl_down_sync(0xffffffffu, bi2, off);
                    better(ov, oi, bv2, bi2);
                }
                if (lane == 0) { s_pv[rr * NSEG + sg] = bv2; s_pi[rr * NSEG + sg] = bi2; }
            }
        }
        __syncthreads();
    }

    if (tid < KCL) {
        g_wr[b * KCL + tid] = s_wr[tid];
        g_wc[b * KCL + tid] = s_wc[tid];
        g_maxv[b * KCL + tid] = s_mv[tid];
    }
}

// ---------------------------------------------------------------------------
// eq: single fused first-occurrence pass over the ORIGINAL input for all 6
// max values. Value at scan i is orig unless covered by window j<i (then 0,
// which never matches mv_i > 0). Matches are rare -> atomicMin (commutative,
// deterministic). grid (NB, 32).
// ---------------------------------------------------------------------------
__global__ __launch_bounds__(256)
void eq_kernel(const float* __restrict__ in) {
    const int b = blockIdx.x, cb = blockIdx.y, tid = threadIdx.x;

    __shared__ float s_mv[KCL];
    __shared__ int   s_wr[KCL], s_wc[KCL];
    __shared__ float s_lo;

    if (tid < KCL) {
        s_mv[tid] = g_maxv[b * KCL + tid];
        s_wr[tid] = g_wr[b * KCL + tid];
        s_wc[tid] = g_wc[b * KCL + tid];
    }
    __syncthreads();
    if (tid == 0) {
        float lo = s_mv[0];
        #pragma unroll
        for (int i = 1; i < KCL; i++) lo = fminf(lo, s_mv[i]);
        s_lo = lo;
    }
    __syncthreads();
    const float lo = s_lo;

    const float4* h4 = (const float4*)(in + (size_t)b * H * H);
    const int b0 = cb * CE4, e0 = min(NE4, b0 + CE4);
    for (int t4 = b0 + tid; t4 < e0; t4 += 256) {
        float4 v = h4[t4];
        float m4 = fmaxf(fmaxf(v.x, v.y), fmaxf(v.z, v.w));
        if (m4 < lo) continue;                       // fast path: no match possible
        #pragma unroll
        for (int u = 0; u < 4; u++) {
            float val = (u == 0) ? v.x : (u == 1) ? v.y : (u == 2) ? v.z : v.w;
            int id = t4 * 4 + u;
            #pragma unroll
            for (int i = 0; i < KCL; i++) {
                if (val == s_mv[i]) {
                    int y = id / H, x = id - y * H;
                    bool cov = false;
                    for (int j = 0; j < i; j++)
                        if ((unsigned)(y - s_wr[j]) < 5u && (unsigned)(x - s_wc[j]) < 5u) cov = true;
                    if (!cov) atomicMin(&g_eqmin[b * KCL + i], id);
                }
            }
        }
    }
}

// ---------------------------------------------------------------------------
// refine: warp-per-cluster mean shift (THR=12 -> 26x26 bbox, w = hm*m/d^2),
// then rounding + clamped 4x4 confidence windows on the ORIGINAL heatmap.
// ---------------------------------------------------------------------------
__global__ __launch_bounds__(192)
void refine_kernel(const float* __restrict__ in, float* __restrict__ out) {
    const int b = blockIdx.x, tid = threadIdx.x;
    const int wid = tid >> 5, lane = tid & 31;
    const float* hm = in + (size_t)b * H * H;

    __shared__ float cly[KCL], clx[KCL], nly[KCL], nlx[KCL];

    if (tid < KCL) {
        int fh = g_eqmin[b * KCL + tid];
        cly[tid] = (float)(fh / H);
        clx[tid] = (float)(fh % H);
    }
    __syncthreads();

    for (int it = 0; it < ITERS; it++) {
        {
            const int k = wid;   // one warp per cluster
            float cy = cly[k], cx = clx[k];
            int y0 = max(0, (int)floorf(cy - 12.0f));
            int y1 = min(H - 1, (int)ceilf(cy + 12.0f));
            int x0 = max(0, (int)floorf(cx - 12.0f));
            int x1 = min(H - 1, (int)ceilf(cx + 12.0f));
            int w  = x1 - x0 + 1;
            int nb = (y1 - y0 + 1) * w;

            float sy = 0.0f, sx = 0.0f, sw = 0.0f;
            for (int t = lane; t < nb; t += 32) {
                int y = y0 + t / w;
                int x = x0 + t % w;
                float dy = (float)y - cy, dx = (float)x - cx;
                float d2 = fmaxf(dy * dy + dx * dx, 1e-6f);
                if (d2 < 144.0f) {
                    float m2 = d2;
                    #pragma unroll
                    for (int k2 = 0; k2 < KCL; k2++) {
                        float ey = (float)y - cly[k2], ex = (float)x - clx[k2];
                        m2 = fminf(m2, fmaxf(ey * ey + ex * ex, 1e-6f));
                    }
                    float wgt = hm[y * H + x] * sqrtf(m2) / d2;
                    sy += wgt * (float)y;
                    sx += wgt * (float)x;
                    sw += wgt;
                }
            }
            #pragma unroll
            for (int off = 16; off; off >>= 1) {
                sy += __shfl_down_sync(0xffffffffu, sy, off);
                sx += __shfl_down_sync(0xffffffffu, sx, off);
                sw += __shfl_down_sync(0xffffffffu, sw, off);
            }
            if (lane == 0) { nly[k] = sy / sw; nlx[k] = sx / sw; }
        }
        __syncthreads();
        if (tid < KCL) { cly[tid] = nly[tid]; clx[tid] = nlx[tid]; }
        __syncthreads();
    }

    if (tid < KCL) {
        int iy = (int)rintf(cly[tid]);   // round-half-to-even == jnp.round
        int ix = (int)rintf(clx[tid]);
        out[(b * KCL + tid) * 2 + 0] = (float)iy;
        out[(b * KCL + tid) * 2 + 1] = (float)ix;
        int sy0 = min(max(iy - 2, 0), H - 4);   // dynamic_slice clamp
        int sx0 = min(max(ix - 2, 0), H - 4);
        float c = 0.0f;
        #pragma unroll
        for (int di = 0; di < 4; di++)
            #pragma unroll
            for (int dj = 0; dj < 4; dj++)
                c += hm[(sy0 + di) * H + (sx0 + dj)];
        out[NB * KCL * 2 + b * KCL + tid] = c;
    }
}

extern "C" void kernel_launch(void* const* d_in, const int* in_sizes, int n_in,
                              void* d_out, int out_size) {
    const float* hm = (const float*)d_in[0];
    float* out = (float*)d_out;

    scan0_kernel<<<dim3(NB, NCH0), 256>>>(hm);
    final6_kernel<<<NB, 256>>>(hm);
    eq_kernel<<<dim3(NB, NCHE), 256>>>(hm);
    refine_kernel<<<NB, 192>>>(hm, out);
}